// round 10
// baseline (speedup 1.0000x reference)
#include <cuda_runtime.h>
#include <cstdint>

// z_e: [32,64,64,64] fp32 -> N=131072 rows, D=64; codebook: [512,64] fp32
// out: z_q (N*D fp32, raw reshape) then indices (N as fp32)
#define NROWS   131072
#define DDIM    64
#define KCB     512
#define TILE_M  128
#define NTILES  (NROWS / TILE_M)    // 1024
#define NCTAS   148
#define TPB     128
#define STR     68                  // padded smem stride (floats) -> conflict-free
#define EPS     2e-4f               // rescue margin (>> worst-case tf32 filter error)

// SMEM layout (float indices)
#define F_AHI   0
#define F_BHI   (F_AHI + TILE_M * STR)     // 8704
#define F_EN    (F_BHI + KCB * STR)        // 43520
#define F_XN    (F_EN + KCB)               // 44032
#define F_D1    (F_XN + TILE_M)            // 44160
#define F_D2    (F_D1 + TILE_M)            // 44288
#define F_K1    (F_D2 + TILE_M)            // 44416
#define SMEM_FLOATS (F_K1 + TILE_M)        // 44544
#define SMEM_BYTES  (SMEM_FLOATS * 4)      // 178176 B

__device__ int g_cnt;
__device__ int g_flags[NROWS];

__device__ __forceinline__ uint32_t f2tf32(float v) {
    uint32_t r; asm("cvt.rna.tf32.f32 %0, %1;" : "=r"(r) : "f"(v)); return r;
}
__device__ __forceinline__ void mma_tf32(float* c, const uint32_t* a,
                                         uint32_t b0, uint32_t b1) {
    asm volatile(
        "mma.sync.aligned.m16n8k8.row.col.f32.tf32.tf32.f32 "
        "{%0,%1,%2,%3}, {%4,%5,%6,%7}, {%8,%9}, {%0,%1,%2,%3};"
        : "+f"(c[0]), "+f"(c[1]), "+f"(c[2]), "+f"(c[3])
        : "r"(a[0]), "r"(a[1]), "r"(a[2]), "r"(a[3]), "r"(b0), "r"(b1));
}

// SACRED: XLA row-reduction tree for sum of squares over 64 f32 (proven R4/R6).
__device__ __forceinline__ float xla_row_sumsq(const float* __restrict__ x)
{
    float t[32];
    #pragma unroll
    for (int l = 0; l < 32; ++l)
        t[l] = __fadd_rn(__fmul_rn(x[2 * l], x[2 * l]),
                         __fmul_rn(x[2 * l + 1], x[2 * l + 1]));
    #pragma unroll
    for (int off = 16; off >= 1; off >>= 1)
        #pragma unroll
        for (int l = 0; l < off; ++l)
            t[l] = __fadd_rn(t[l], t[l + off]);
    return t[0];
}

__global__ void vq_reset() { if (threadIdx.x == 0) g_cnt = 0; }

__global__ __launch_bounds__(TPB, 1)
void vq_mma(const float* __restrict__ z_e,
            const float* __restrict__ cb,
            float* __restrict__ out,
            int write_idx)
{
    extern __shared__ float smf[];
    uint32_t* smu = (uint32_t*)smf;
    int* smk = (int*)(smf + F_K1);
    const int tid  = threadIdx.x;
    const int wid  = tid >> 5;
    const int lane = tid & 31;
    const int g = lane >> 2;
    const int q = lane & 3;
    const int mb = wid * 32;

    // ---- stage B: all 512 codewords, tf32 (single split) + SACRED en ----
    for (int i = tid; i < KCB * DDIM; i += TPB) {
        const int n = i >> 6, k = i & 63;
        smu[F_BHI + n * STR + k] = f2tf32(cb[i]);
    }
    for (int n = tid; n < KCB; n += TPB)
        smf[F_EN + n] = xla_row_sumsq(cb + n * DDIM);
    __syncthreads();

    for (int t = blockIdx.x; t < NTILES; t += NCTAS) {
        const int row = t * TILE_M + tid;
        // ---- stage A (NCHW gather) + SACRED xn + tf32 ----
        {
            float x[DDIM];
            const long long base = (long long)(row >> 12) * 262144 + (row & 4095);
            #pragma unroll
            for (int c = 0; c < DDIM; ++c)
                x[c] = z_e[base + (long long)c * 4096];
            smf[F_XN + tid] = xla_row_sumsq(x);
            #pragma unroll
            for (int c = 0; c < DDIM; ++c)
                smu[F_AHI + tid * STR + c] = f2tf32(x[c]);
        }
        __syncthreads();

        // per-thread (d1,k1,d2) over its 128 cols, rows mb+g+ri*8
        float d1[4] = {3.4e38f, 3.4e38f, 3.4e38f, 3.4e38f};
        float d2[4] = {3.4e38f, 3.4e38f, 3.4e38f, 3.4e38f};
        int   k1[4] = {0, 0, 0, 0};
        float xnr[4];
        #pragma unroll
        for (int ri = 0; ri < 4; ++ri)
            xnr[ri] = smf[F_XN + mb + g + ri * 8];

        #pragma unroll 1
        for (int chunk = 0; chunk < 8; ++chunk) {      // 64 cols each
            float acc[2][8][4];
            #pragma unroll
            for (int a = 0; a < 2; ++a)
                #pragma unroll
                for (int b = 0; b < 8; ++b)
                    #pragma unroll
                    for (int c = 0; c < 4; ++c) acc[a][b][c] = 0.f;

            #pragma unroll
            for (int kb = 0; kb < DDIM; kb += 8) {
                uint32_t a0[4], a1[4];
                const uint32_t* A0 = smu + F_AHI + (mb + g) * STR + kb + q;
                a0[0] = A0[0];           a0[1] = A0[8 * STR];
                a0[2] = A0[4];           a0[3] = A0[8 * STR + 4];
                const uint32_t* A1 = A0 + 16 * STR;
                a1[0] = A1[0];           a1[1] = A1[8 * STR];
                a1[2] = A1[4];           a1[3] = A1[8 * STR + 4];
                #pragma unroll
                for (int s8 = 0; s8 < 8; ++s8) {
                    const int n0 = chunk * 64 + s8 * 8;
                    const uint32_t* Bp = smu + F_BHI + (n0 + g) * STR + kb + q;
                    const uint32_t b0 = Bp[0], b1 = Bp[4];
                    mma_tf32(acc[0][s8], a0, b0, b1);
                    mma_tf32(acc[1][s8], a1, b0, b1);
                }
            }
            // epilogue: filter dist + (d1,k1,d2) tracking (ascending k)
            #pragma unroll
            for (int s8 = 0; s8 < 8; ++s8) {
                const int c0 = chunk * 64 + s8 * 8 + 2 * q;
                const float en0 = smf[F_EN + c0];
                const float en1 = smf[F_EN + c0 + 1];
                #pragma unroll
                for (int rg = 0; rg < 2; ++rg) {
                    #pragma unroll
                    for (int hr = 0; hr < 2; ++hr) {
                        const int ri = rg * 2 + hr;
                        const float dd0 = __fsub_rn(__fadd_rn(xnr[ri], en0),
                                                    __fmul_rn(2.f, acc[rg][s8][hr * 2 + 0]));
                        const float dd1 = __fsub_rn(__fadd_rn(xnr[ri], en1),
                                                    __fmul_rn(2.f, acc[rg][s8][hr * 2 + 1]));
                        if (dd0 < d1[ri]) { d2[ri] = d1[ri]; d1[ri] = dd0; k1[ri] = c0; }
                        else if (dd0 < d2[ri]) d2[ri] = dd0;
                        if (dd1 < d1[ri]) { d2[ri] = d1[ri]; d1[ri] = dd1; k1[ri] = c0 + 1; }
                        else if (dd1 < d2[ri]) d2[ri] = dd1;
                    }
                }
            }
        }

        // quad merge of (d1,k1,d2): lexicographic best; union second-best
        #pragma unroll
        for (int ri = 0; ri < 4; ++ri) {
            float a = d1[ri], b = d2[ri]; int i = k1[ri];
            #pragma unroll
            for (int off = 1; off <= 2; off <<= 1) {
                const float oa = __shfl_xor_sync(0xffffffffu, a, off);
                const float ob = __shfl_xor_sync(0xffffffffu, b, off);
                const int   oi = __shfl_xor_sync(0xffffffffu, i, off);
                const float hi = fmaxf(a, oa);
                b = fminf(fminf(b, ob), hi);
                if (oa < a || (oa == a && oi < i)) { a = oa; i = oi; }
            }
            d1[ri] = a; d2[ri] = b; k1[ri] = i;
        }
        if (q == 0) {
            #pragma unroll
            for (int ri = 0; ri < 4; ++ri) {
                const int lr = mb + g + ri * 8;
                smf[F_D1 + lr] = d1[ri];
                smf[F_D2 + lr] = d2[ri];
                smk[lr] = k1[ri];
            }
        }
        __syncthreads();

        // outputs + rescue flagging (thread tid owns row tid of the tile)
        {
            const float a = smf[F_D1 + tid];
            const float b = smf[F_D2 + tid];
            const int   bi = smk[tid];
            const float4* src = (const float4*)(cb + (size_t)bi * DDIM);
            float4* o = (float4*)(out + (size_t)row * DDIM);
            #pragma unroll
            for (int j = 0; j < DDIM / 4; ++j) o[j] = src[j];
            if (write_idx) out[(size_t)NROWS * DDIM + row] = (float)bi;
            if (b - a <= EPS) {
                const int p = atomicAdd(&g_cnt, 1);
                g_flags[p] = row;
            }
        }
        __syncthreads();   // before next tile overwrites F_AHI/F_XN/results
    }
}

// Exact scalar rescue for flagged rows — bitwise the proven R6 path.
__global__ __launch_bounds__(128, 1)
void vq_rescue(const float* __restrict__ z_e,
               const float* __restrict__ cb,
               float* __restrict__ out,
               int write_idx)
{
    const int lane = threadIdx.x & 31;
    const int wg   = (blockIdx.x * blockDim.x + threadIdx.x) >> 5;
    const int nw   = (gridDim.x * blockDim.x) >> 5;
    const int cnt  = g_cnt;

    for (int i = wg; i < cnt; i += nw) {
        const int row = g_flags[i];
        float x[DDIM];
        const long long base = (long long)(row >> 12) * 262144 + (row & 4095);
        #pragma unroll
        for (int c = 0; c < DDIM; ++c)
            x[c] = z_e[base + (long long)c * 4096];
        const float xn = xla_row_sumsq(x);   // SACRED

        float best = 3.402823466e38f;
        int   bi   = KCB;
        for (int k = lane; k < KCB; k += 32) {
            const float* e = cb + (size_t)k * DDIM;
            const float en = xla_row_sumsq(e);   // SACRED
            float p0 = 0.f, p1 = 0.f, p2 = 0.f, p3 = 0.f;
            #pragma unroll
            for (int j = 0; j < DDIM / 4; ++j) {
                p0 = fmaf(x[4 * j + 0], e[4 * j + 0], p0);
                p1 = fmaf(x[4 * j + 1], e[4 * j + 1], p1);
                p2 = fmaf(x[4 * j + 2], e[4 * j + 2], p2);
                p3 = fmaf(x[4 * j + 3], e[4 * j + 3], p3);
            }
            const float dot = (p0 + p1) + (p2 + p3);   // proven-free order
            // SACRED final rounding
            const float d = __fsub_rn(__fadd_rn(xn, en), __fmul_rn(2.f, dot));
            if (d < best) { best = d; bi = k; }        // ascending k, strict <
        }
        // lexicographic (d, k) merge across lanes -> first-index tie semantics
        #pragma unroll
        for (int off = 16; off >= 1; off >>= 1) {
            const float od = __shfl_xor_sync(0xffffffffu, best, off);
            const int   oi = __shfl_xor_sync(0xffffffffu, bi, off);
            if (od < best || (od == best && oi < bi)) { best = od; bi = oi; }
        }
        // overwrite outputs for this row
        const float4* src = (const float4*)(cb + (size_t)bi * DDIM);
        if (lane < DDIM / 4)
            ((float4*)(out + (size_t)row * DDIM))[lane] = src[lane];
        if (write_idx && lane == 0)
            out[(size_t)NROWS * DDIM + row] = (float)bi;
    }
}

extern "C" void kernel_launch(void* const* d_in, const int* in_sizes, int n_in,
                              void* d_out, int out_size)
{
    const float* z_e = (const float*)d_in[0];
    const float* cb  = (const float*)d_in[1];
    if (n_in >= 2 && in_sizes[0] == KCB * DDIM && in_sizes[1] == NROWS * DDIM) {
        const float* t = z_e; z_e = cb; cb = t;   // defensive input-order swap
    }
    const int write_idx = (out_size >= NROWS * DDIM + NROWS) ? 1 : 0;

    vq_reset<<<1, 32>>>();
    cudaFuncSetAttribute(vq_mma, cudaFuncAttributeMaxDynamicSharedMemorySize,
                         SMEM_BYTES);
    vq_mma<<<NCTAS, TPB, SMEM_BYTES>>>(z_e, cb, (float*)d_out, write_idx);
    vq_rescue<<<128, 128>>>(z_e, cb, (float*)d_out, write_idx);
}